// round 4
// baseline (speedup 1.0000x reference)
#include <cuda_runtime.h>

// AOLayer: out[b,n,a] = ang * rad, B=512,N=32,A=256,P=6.
// Round 4: MUFU EX2 dispatch is the binding resource (8 issue slots per
// warp-EX2). Halve the MUFU instruction count with ex2.approx.f16x2:
// one MUFU op computes exp2 for both rows of the pair. Args built in f32,
// accumulation stays f32x2. Expected rel_err ~3e-4 (< 1e-3 threshold).

#define A_DIM 256
#define P_DIM 6
#define BN_DIM (512 * 32)
#define ROWS_PER_BLOCK 16
#define NPAIRS (ROWS_PER_BLOCK / 2)

typedef unsigned long long u64;

__device__ __forceinline__ u64 pack2(float lo, float hi) {
    u64 r;
    asm("mov.b64 %0, {%1, %2};" : "=l"(r) : "f"(lo), "f"(hi));
    return r;
}
__device__ __forceinline__ u64 add2(u64 a, u64 b) {
    u64 r; asm("add.rn.f32x2 %0, %1, %2;" : "=l"(r) : "l"(a), "l"(b)); return r;
}
__device__ __forceinline__ u64 mul2(u64 a, u64 b) {
    u64 r; asm("mul.rn.f32x2 %0, %1, %2;" : "=l"(r) : "l"(a), "l"(b)); return r;
}
__device__ __forceinline__ u64 fma2(u64 a, u64 b, u64 c) {
    u64 r; asm("fma.rn.f32x2 %0, %1, %2, %3;" : "=l"(r) : "l"(a), "l"(b), "l"(c)); return r;
}

// exp2 of both packed halves via ONE MUFU instruction (ex2.approx.f16x2).
// f32x2 -> f16x2 -> ex2 -> 2x f32. Result rel err ~2^-11 (threshold 1e-3).
__device__ __forceinline__ u64 exp2_pair_f16(u64 x) {
    u64 r;
    asm("{\n\t"
        ".reg .f32 lo, hi;\n\t"
        ".reg .b16 elo, ehi;\n\t"
        ".reg .b32 hp;\n\t"
        "mov.b64 {lo, hi}, %1;\n\t"
        "cvt.rn.f16x2.f32 hp, hi, lo;\n\t"   // first src -> high half
        "ex2.approx.f16x2 hp, hp;\n\t"
        "mov.b32 {elo, ehi}, hp;\n\t"
        "cvt.f32.f16 lo, elo;\n\t"
        "cvt.f32.f16 hi, ehi;\n\t"
        "mov.b64 %0, {lo, hi};\n\t"
        "}" : "=l"(r) : "l"(x));
    return r;
}

__global__ void __launch_bounds__(A_DIM) aolayer_kernel(
    const float* __restrict__ pos,      // [BN, 3]
    const float* __restrict__ centers,  // [A, 3]
    const float* __restrict__ exps,     // [A, P]
    const float* __restrict__ coeffs,   // [A, P]
    const int*   __restrict__ powers,   // [A, 3]
    float* __restrict__ out)            // [BN, A]
{
    const int a = threadIdx.x;

    // ---- per-atom constants (once per block) ----
    const float cx = centers[a * 3 + 0];
    const float cy = centers[a * 3 + 1];
    const float cz = centers[a * 3 + 2];
    const u64 ncx2 = pack2(-cx, -cx);
    const u64 ncy2 = pack2(-cy, -cy);
    const u64 ncz2 = pack2(-cz, -cz);

    const float NEG_LOG2E = -1.4426950408889634f;
    u64 ep2[P_DIM], co2[P_DIM];
#pragma unroll
    for (int p = 0; p < P_DIM; p++) {
        float e = exps[a * P_DIM + p] * NEG_LOG2E;
        float c = coeffs[a * P_DIM + p];
        ep2[p] = pack2(e, e);
        co2[p] = pack2(c, c);
    }

    const int px = powers[a * 3 + 0];
    const int py = powers[a * 3 + 1];
    const int pz = powers[a * 3 + 2];
    const bool lx = (px >= 1), qx = (px == 2);
    const bool ly = (py >= 1), qy = (py == 2);
    const bool lz = (pz >= 1), qz = (pz == 2);

    // ---- stage pre-packed pos pairs: spos2[pair*3 + dim] = {row 2p, row 2p+1} ----
    __shared__ u64 spos2[NPAIRS * 3];
    const int row0 = blockIdx.x * ROWS_PER_BLOCK;
    if (threadIdx.x < NPAIRS * 3) {
        const int pr = threadIdx.x / 3;
        const int d  = threadIdx.x % 3;
        const float v0 = pos[(row0 + 2 * pr) * 3 + d];
        const float v1 = pos[(row0 + 2 * pr + 1) * 3 + d];
        spos2[threadIdx.x] = pack2(v0, v1);
    }
    __syncthreads();

    float* out_base = out + (size_t)row0 * A_DIM + a;

#pragma unroll
    for (int pr = 0; pr < NPAIRS; pr++) {
        const u64 dxp = add2(spos2[pr * 3 + 0], ncx2);
        const u64 dyp = add2(spos2[pr * 3 + 1], ncy2);
        const u64 dzp = add2(spos2[pr * 3 + 2], ncz2);

        u64 r2p = mul2(dzp, dzp);
        r2p = fma2(dyp, dyp, r2p);
        r2p = fma2(dxp, dxp, r2p);

        // radial: 6 exps per row, 2 rows -> 6 f16x2 MUFU instructions total.
        // Two independent accumulators to relax the FMA chain.
        u64 rad0 = mul2(co2[0], exp2_pair_f16(mul2(ep2[0], r2p)));
        u64 rad1 = mul2(co2[1], exp2_pair_f16(mul2(ep2[1], r2p)));
        rad0 = fma2(co2[2], exp2_pair_f16(mul2(ep2[2], r2p)), rad0);
        rad1 = fma2(co2[3], exp2_pair_f16(mul2(ep2[3], r2p)), rad1);
        rad0 = fma2(co2[4], exp2_pair_f16(mul2(ep2[4], r2p)), rad0);
        rad1 = fma2(co2[5], exp2_pair_f16(mul2(ep2[5], r2p)), rad1);

        u64 o = add2(rad0, rad1);

        // angular as predicated packed muls (predicates loop-invariant)
        if (lx) o = mul2(o, dxp);
        if (qx) o = mul2(o, dxp);
        if (ly) o = mul2(o, dyp);
        if (qy) o = mul2(o, dyp);
        if (lz) o = mul2(o, dzp);
        if (qz) o = mul2(o, dzp);

        float o0, o1;
        asm("mov.b64 {%0, %1}, %2;" : "=f"(o0), "=f"(o1) : "l"(o));
        out_base[(2 * pr) * A_DIM] = o0;
        out_base[(2 * pr + 1) * A_DIM] = o1;
    }
}

extern "C" void kernel_launch(void* const* d_in, const int* in_sizes, int n_in,
                              void* d_out, int out_size) {
    const float* pos     = (const float*)d_in[0];
    const float* centers = (const float*)d_in[1];
    const float* exps    = (const float*)d_in[2];
    const float* coeffs  = (const float*)d_in[3];
    const int*   powers  = (const int*)d_in[4];
    float* out = (float*)d_out;

    dim3 grid(BN_DIM / ROWS_PER_BLOCK);  // 1024 blocks
    dim3 block(A_DIM);                   // 256 threads, one per atom
    aolayer_kernel<<<grid, block>>>(pos, centers, exps, coeffs, powers, out);
}

// round 5
// speedup vs baseline: 1.0226x; 1.0226x over previous
#include <cuda_runtime.h>

// AOLayer: out[b,n,a] = ang * rad, B=512,N=32,A=256,P=6.
// Round 5: minimal-issue-slot scalar kernel. Evidence from r1-r4: bound by
// total issued instructions (packed f32x2 = 2 slots, f16x2 ex2 pays 3 cvts).
// So: scalar f32, 6 MUFU ex2 per element, predicated angular muls (no SELs),
// dual accumulators, zero pack/cvt traffic.

#define A_DIM 256
#define P_DIM 6
#define BN_DIM (512 * 32)
#define ROWS_PER_BLOCK 16

__device__ __forceinline__ float ex2f(float x) {
    float r;
    asm("ex2.approx.f32 %0, %1;" : "=f"(r) : "f"(x));
    return r;
}

__global__ void __launch_bounds__(A_DIM) aolayer_kernel(
    const float* __restrict__ pos,      // [BN, 3]
    const float* __restrict__ centers,  // [A, 3]
    const float* __restrict__ exps,     // [A, P]
    const float* __restrict__ coeffs,   // [A, P]
    const int*   __restrict__ powers,   // [A, 3]
    float* __restrict__ out)            // [BN, A]
{
    const int a = threadIdx.x;

    // ---- per-atom constants (once per block) ----
    const float ncx = -centers[a * 3 + 0];
    const float ncy = -centers[a * 3 + 1];
    const float ncz = -centers[a * 3 + 2];

    const float NEG_LOG2E = -1.4426950408889634f;
    float ep[P_DIM], co[P_DIM];
#pragma unroll
    for (int p = 0; p < P_DIM; p++) {
        ep[p] = exps[a * P_DIM + p] * NEG_LOG2E;
        co[p] = coeffs[a * P_DIM + p];
    }

    const int px = powers[a * 3 + 0];
    const int py = powers[a * 3 + 1];
    const int pz = powers[a * 3 + 2];
    // loop-invariant predicates -> ISETPs hoisted out of the unrolled loop
    const bool lx = (px >= 1), qx = (px == 2);
    const bool ly = (py >= 1), qy = (py == 2);
    const bool lz = (pz >= 1), qz = (pz == 2);

    // ---- stage pos rows into shared memory ----
    __shared__ float spos[ROWS_PER_BLOCK * 3];
    const int row0 = blockIdx.x * ROWS_PER_BLOCK;
    if (threadIdx.x < ROWS_PER_BLOCK * 3) {
        spos[threadIdx.x] = pos[row0 * 3 + threadIdx.x];
    }
    __syncthreads();

    float* out_base = out + (size_t)row0 * A_DIM + a;

#pragma unroll
    for (int r = 0; r < ROWS_PER_BLOCK; r++) {
        const float dx = spos[r * 3 + 0] + ncx;
        const float dy = spos[r * 3 + 1] + ncy;
        const float dz = spos[r * 3 + 2] + ncz;

        const float r2 = fmaf(dx, dx, fmaf(dy, dy, dz * dz));

        // radial: dual accumulators, 6 MUFU + 6 FMUL + 6 FMA-pipe accumulate
        float rad0 = co[0] * ex2f(ep[0] * r2);
        float rad1 = co[1] * ex2f(ep[1] * r2);
        rad0 = fmaf(co[2], ex2f(ep[2] * r2), rad0);
        rad1 = fmaf(co[3], ex2f(ep[3] * r2), rad1);
        rad0 = fmaf(co[4], ex2f(ep[4] * r2), rad0);
        rad1 = fmaf(co[5], ex2f(ep[5] * r2), rad1);

        float o = rad0 + rad1;

        // angular folded in as predicated muls (predicates loop-invariant)
        if (lx) o *= dx;
        if (qx) o *= dx;
        if (ly) o *= dy;
        if (qy) o *= dy;
        if (lz) o *= dz;
        if (qz) o *= dz;

        out_base[r * A_DIM] = o;
    }
}

extern "C" void kernel_launch(void* const* d_in, const int* in_sizes, int n_in,
                              void* d_out, int out_size) {
    const float* pos     = (const float*)d_in[0];
    const float* centers = (const float*)d_in[1];
    const float* exps    = (const float*)d_in[2];
    const float* coeffs  = (const float*)d_in[3];
    const int*   powers  = (const int*)d_in[4];
    float* out = (float*)d_out;

    dim3 grid(BN_DIM / ROWS_PER_BLOCK);  // 1024 blocks
    dim3 block(A_DIM);                   // 256 threads, one per atom
    aolayer_kernel<<<grid, block>>>(pos, centers, exps, coeffs, powers, out);
}